// round 11
// baseline (speedup 1.0000x reference)
#include <cuda_runtime.h>
#include <math.h>

// Problem constants
#define G2   64
#define Hh   64
#define Aa   1024
#define Ss   32
#define Pp   4096
#define Bb   2048
#define NBLK 148
#define NTHR 256

typedef unsigned long long ull;

// -------- packed f32x2 helpers --------
__device__ __forceinline__ ull pk2(float lo, float hi) {
    ull r; asm("mov.b64 %0, {%1,%2};" : "=l"(r) : "f"(lo), "f"(hi)); return r;
}
__device__ __forceinline__ void upk2(ull v, float& lo, float& hi) {
    asm("mov.b64 {%0,%1}, %2;" : "=f"(lo), "=f"(hi) : "l"(v));
}
__device__ __forceinline__ ull ffma2(ull a, ull b, ull c) {
    ull d; asm("fma.rn.f32x2 %0, %1, %2, %3;" : "=l"(d) : "l"(a), "l"(b), "l"(c));
    return d;
}

// -------- device scratch (no allocations allowed) --------
__device__ float g_occ[Bb * G2];
__device__ float g_c[Bb * Aa];
__device__ float g_ctx[Bb];
__device__ float g_wc[70 * Aa];
__device__ float g_y[Bb * Aa];
__device__ float g_sum[Aa];
__device__ float g_sumsq[Aa];
__device__ unsigned g_bar_count = 0;
__device__ unsigned g_bar_gen   = 0;   // monotone generation; replay-safe

// -------- grid-wide barrier (all 148 blocks co-resident) --------
__device__ __forceinline__ void grid_barrier() {
    __syncthreads();
    if (threadIdx.x == 0) {
        __threadfence();
        unsigned gen = *((volatile unsigned*)&g_bar_gen);   // read BEFORE arriving
        if (atomicAdd(&g_bar_count, 1u) == (unsigned)(gridDim.x - 1)) {
            g_bar_count = 0;            // safe: no one touches count until gen flips
            __threadfence();
            atomicAdd(&g_bar_gen, 1u);  // release
        } else {
            while (*((volatile unsigned*)&g_bar_gen) == gen) { __nanosleep(64); }
            __threadfence();
        }
    }
    __syncthreads();
}

// ---------------------------------------------------------------------------
__global__ __launch_bounds__(NTHR, 2)
void fused_kernel(const float* __restrict__ h,
                  const float* __restrict__ end_pos,
                  const float* __restrict__ rel_pos,
                  const float* __restrict__ scene,
                  const float* __restrict__ We,
                  const float* __restrict__ be,
                  const float* __restrict__ Wd,
                  const float* __restrict__ bd,
                  const float* __restrict__ wf,
                  const float* __restrict__ Wo,
                  const float* __restrict__ bo,
                  const float* __restrict__ Wm,
                  const float* __restrict__ bm,
                  const float* __restrict__ gamma,
                  const float* __restrict__ beta,
                  float* __restrict__ out) {
    __shared__ __align__(16) float smem[2432];   // 9728 B, unioned across phases
    const int tid = threadIdx.x;

    // ================= PHASE 1: zero scratch =================
    {
        const float4 z = make_float4(0.f, 0.f, 0.f, 0.f);
        for (int i = blockIdx.x * NTHR + tid; i < 51200; i += NBLK * NTHR) {
            if (i < 32768)                 reinterpret_cast<float4*>(g_occ)[i] = z;
            else if (i < 32768 + 17920)    reinterpret_cast<float4*>(g_wc)[i - 32768] = z;
            else if (i < 32768 + 18176)    reinterpret_cast<float4*>(g_sum)[i - 50688] = z;
            else                           reinterpret_cast<float4*>(g_sumsq)[i - 50944] = z;
        }
    }
    grid_barrier();

    // ================= PHASE 2: c-GEMM, occupancy, Wc =================
    // units: [0,512) c | [512,768) occ | [768,1280) wc
    for (int u = blockIdx.x; u < 1280; u += NBLK) {
        if (u < 512) {
            // ---- c[b,a] = h@W_dec + b_dec + b_enc, 16 rows x 256 a-cols ----
            int a  = (u & 3) * 256 + tid;
            int b0 = (u >> 2) * 16;
            float* hp = smem;   // hp[k*16+bl]
            for (int idx = tid; idx < 16 * Hh; idx += NTHR) {
                int bl = idx >> 6, k = idx & 63;
                hp[k * 16 + bl] = h[(b0 + bl) * Hh + k];
            }
            __syncthreads();
            ull acc[8] = {0, 0, 0, 0, 0, 0, 0, 0};
            const ulonglong2* hpu = reinterpret_cast<const ulonglong2*>(hp);
#pragma unroll 8
            for (int k = 0; k < Hh; k++) {
                float w = Wd[k * Aa + a];
                ull ww = pk2(w, w);
#pragma unroll
                for (int jj = 0; jj < 4; jj++) {
                    ulonglong2 v = hpu[k * 4 + jj];
                    acc[2 * jj]     = ffma2(v.x, ww, acc[2 * jj]);
                    acc[2 * jj + 1] = ffma2(v.y, ww, acc[2 * jj + 1]);
                }
            }
            float bias = bd[a] + be[a];
#pragma unroll
            for (int j = 0; j < 8; j++) {
                float lo, hi; upk2(acc[j], lo, hi);
                g_c[(size_t)(b0 + 2 * j) * Aa + a]     = lo + bias;
                g_c[(size_t)(b0 + 2 * j + 1) * Aa + a] = hi + bias;
            }
        } else if (u < 768) {
            // ---- occupancy: 8 pedestrians per unit ----
            int v = u - 512;
            int grp = v & 7;
            int s   = v >> 3;
            int pedbase = s * 64 + grp * 8;
            int*    bins  = reinterpret_cast<int*>(smem);          // 8*64 ints
            float4* boxsh = reinterpret_cast<float4*>(smem + 512); // 8 float4

            for (int i = tid; i < 8 * G2; i += NTHR) bins[i] = 0;
            if (tid < 8) {
                float ex = end_pos[(pedbase + tid) * 2 + 0];
                float ey = end_pos[(pedbase + tid) * 2 + 1];
                boxsh[tid] = make_float4(ex - 1.0f, ey + 1.0f, ex + 1.0f, ey - 1.0f);
            }
            __syncthreads();
            float4 bx[8];
#pragma unroll
            for (int j = 0; j < 8; j++) bx[j] = boxsh[j];

            const float2* sc = reinterpret_cast<const float2*>(scene) + (size_t)s * Pp;
            for (int p = tid; p < Pp; p += NTHR) {
                float2 q = sc[p];
#pragma unroll
                for (int j = 0; j < 8; j++) {
                    bool in = (q.x < bx[j].z) && (q.x > bx[j].x) &&
                              (q.y < bx[j].y) && (q.y > bx[j].w);
                    if (in) {
                        float cx = floorf(((q.x - bx[j].x) / 2.0f) * 8.0f);
                        float cy = floorf(((bx[j].y - q.y) / 2.0f) * 8.0f);
                        int cell = (int)(cx + cy * 8.0f);
                        if (cell >= 0 && cell < G2) {
                            atomicAdd(&bins[j * G2 + cell], 1);
                        } else {
                            long flat = (long)(pedbase + j) * G2 + cell;
                            if (flat >= 0 && flat < (long)Bb * G2)
                                atomicAdd(&g_occ[flat], 1.0f);   // rare bleed, exact int adds
                        }
                    }
                }
            }
            __syncthreads();
            for (int i = tid; i < 8 * G2; i += NTHR) {
                int bv = bins[i];
                if (bv) atomicAdd(&g_occ[pedbase * G2 + i], (float)bv);
            }
        } else {
            // ---- Wc partials -> atomic into g_wc ----
            int wcb = u - 768;                  // 0..511
            int a  = (wcb & 3) * 256 + tid;
            int r0 = ((wcb >> 2) & 3) * 18;
            int k0 = (wcb >> 4) * 32;
            float* ws = smem;                    // 9*32*2 pair-interleaved

            for (int idx = tid; idx < 9 * 32; idx += NTHR) {
                int p = idx >> 5, k = idx & 31;
                int r = r0 + 2 * p;
                float v0 = 0.f, v1 = 0.f;
                if (r < 69)       v0 = Wo[r * Aa + k0 + k];
                else if (r == 69) v0 = bo[k0 + k];
                if (r + 1 < 69)       v1 = Wo[(r + 1) * Aa + k0 + k];
                else if (r + 1 == 69) v1 = bo[k0 + k];
                ws[idx * 2]     = v0;
                ws[idx * 2 + 1] = v1;
            }
            __syncthreads();

            ull acc[9];
#pragma unroll
            for (int p = 0; p < 9; p++) acc[p] = 0ull;
            const ulonglong2* wsu = reinterpret_cast<const ulonglong2*>(ws);
#pragma unroll 2
            for (int k = 0; k < 32; k += 2) {
                float w0 = Wm[(size_t)(k0 + k) * Aa + a];
                float w1 = Wm[(size_t)(k0 + k + 1) * Aa + a];
                ull ww0 = pk2(w0, w0), ww1 = pk2(w1, w1);
#pragma unroll
                for (int p = 0; p < 9; p++) {
                    ulonglong2 v = wsu[p * 16 + (k >> 1)];
                    acc[p] = ffma2(v.x, ww0, acc[p]);
                    acc[p] = ffma2(v.y, ww1, acc[p]);
                }
            }
#pragma unroll
            for (int p = 0; p < 9; p++) {
                int r = r0 + 2 * p;
                float lo, hi; upk2(acc[p], lo, hi);
                if (r < 70)     atomicAdd(&g_wc[r * Aa + a], lo);
                if (r + 1 < 70) atomicAdd(&g_wc[(r + 1) * Aa + a], hi);
            }
        }
        __syncthreads();   // smem reuse by next unit
    }
    grid_barrier();

    // ================= PHASE 3: fused e / softmax / ctx =================
    // 128 units x 16 rows; 256 thr = 16 bl x 16 gq, 4 g per thread.
    {
        float* we_s = smem;          // 128
        float* wf_s = smem + 128;    // 128
        float (*c_s)[132] = reinterpret_cast<float(*)[132]>(smem + 256);
        int bl = tid >> 4;
        int gq = tid & 15;
        for (int u = blockIdx.x; u < 128; u += NBLK) {
            int b0 = u * 16;
            int b  = b0 + bl;
            float og[4];
            ull ogw[4], e2[4];
#pragma unroll
            for (int i = 0; i < 4; i++) {
                og[i]  = g_occ[b * G2 + gq * 4 + i];
                ogw[i] = pk2(og[i], og[i]);
                e2[i]  = 0ull;
            }
            for (int a0 = 0; a0 < Aa; a0 += 128) {
                __syncthreads();
                if (tid < 128) { we_s[tid] = We[a0 + tid]; wf_s[tid] = wf[a0 + tid]; }
                for (int i = tid; i < 16 * 128; i += NTHR) {
                    int bi = i >> 7, j = i & 127;
                    c_s[bi][j] = g_c[(size_t)(b0 + bi) * Aa + a0 + j];
                }
                __syncthreads();
                const ull* weu = reinterpret_cast<const ull*>(we_s);
                const ull* wfu = reinterpret_cast<const ull*>(wf_s);
                const ull* cu  = reinterpret_cast<const ull*>(&c_s[bl][0]);
#pragma unroll 4
                for (int jj = 0; jj < 64; jj++) {
                    ull we2 = weu[jj];
                    ull wf2 = wfu[jj];
                    ull c2  = cu[jj];
#pragma unroll
                    for (int i = 0; i < 4; i++) {
                        ull x2 = ffma2(ogw[i], we2, c2);
                        float lo, hi; upk2(x2, lo, hi);
                        lo = fmaxf(lo, 0.0f);
                        hi = fmaxf(hi, 0.0f);
                        e2[i] = ffma2(pk2(lo, hi), wf2, e2[i]);
                    }
                }
            }
            float e[4];
#pragma unroll
            for (int i = 0; i < 4; i++) { float lo, hi; upk2(e2[i], lo, hi); e[i] = lo + hi; }

            float m = fmaxf(fmaxf(e[0], e[1]), fmaxf(e[2], e[3]));
#pragma unroll
            for (int off = 8; off >= 1; off >>= 1)
                m = fmaxf(m, __shfl_xor_sync(0xffffffffu, m, off, 16));
            float s = 0.f, cx = 0.f;
#pragma unroll
            for (int i = 0; i < 4; i++) {
                float ex = __expf(e[i] - m);
                s += ex;
                cx = fmaf(ex, og[i], cx);
            }
#pragma unroll
            for (int off = 8; off >= 1; off >>= 1) {
                s  += __shfl_xor_sync(0xffffffffu, s, off, 16);
                cx += __shfl_xor_sync(0xffffffffu, cx, off, 16);
            }
            if (gq == 0) g_ctx[b] = cx / s;
            __syncthreads();
        }
    }
    grid_barrier();

    // ================= PHASE 4: y = u@Wc + bias, stats atomics =================
    {
        float* us = smem;   // 69*16 floats
        for (int u = blockIdx.x; u < 512; u += NBLK) {
            int a  = (u & 3) * 256 + tid;
            int b0 = (u >> 2) * 16;
            for (int idx = tid; idx < 69 * 16; idx += NTHR) {
                int r = idx >> 4, bl = idx & 15;
                int b = b0 + bl;
                float v;
                if (r == 0)      v = g_ctx[b];
                else if (r < 65) v = h[b * Hh + (r - 1)];
                else if (r < 67) v = end_pos[b * 2 + (r - 65)];
                else             v = rel_pos[b * 2 + (r - 67)];
                us[idx] = v;
            }
            __syncthreads();

            ull acc[8] = {0, 0, 0, 0, 0, 0, 0, 0};
            const ulonglong2* usu = reinterpret_cast<const ulonglong2*>(us);
            const float* wcol = g_wc + a;
            // 4-deep w prefetch (MLP=4) over rows 0..67, then row 68.
            for (int r = 0; r < 68; r += 4) {
                float w0 = wcol[(r + 0) * Aa];
                float w1 = wcol[(r + 1) * Aa];
                float w2 = wcol[(r + 2) * Aa];
                float w3 = wcol[(r + 3) * Aa];
                ull wwv[4] = { pk2(w0, w0), pk2(w1, w1), pk2(w2, w2), pk2(w3, w3) };
#pragma unroll
                for (int rr = 0; rr < 4; rr++) {
#pragma unroll
                    for (int jj = 0; jj < 4; jj++) {
                        ulonglong2 v = usu[(r + rr) * 4 + jj];
                        acc[2 * jj]     = ffma2(v.x, wwv[rr], acc[2 * jj]);
                        acc[2 * jj + 1] = ffma2(v.y, wwv[rr], acc[2 * jj + 1]);
                    }
                }
            }
            {
                float w = wcol[68 * Aa];
                ull ww = pk2(w, w);
#pragma unroll
                for (int jj = 0; jj < 4; jj++) {
                    ulonglong2 v = usu[68 * 4 + jj];
                    acc[2 * jj]     = ffma2(v.x, ww, acc[2 * jj]);
                    acc[2 * jj + 1] = ffma2(v.y, ww, acc[2 * jj + 1]);
                }
            }
            float bias = wcol[69 * Aa] + bm[a];
            float s = 0.f, s2 = 0.f;
#pragma unroll
            for (int j = 0; j < 8; j++) {
                float lo, hi; upk2(acc[j], lo, hi);
                float v0 = lo + bias, v1 = hi + bias;
                g_y[(size_t)(b0 + 2 * j) * Aa + a]     = v0;
                g_y[(size_t)(b0 + 2 * j + 1) * Aa + a] = v1;
                s += v0 + v1;
                s2 = fmaf(v0, v0, s2);
                s2 = fmaf(v1, v1, s2);
            }
            atomicAdd(&g_sum[a], s);
            atomicAdd(&g_sumsq[a], s2);
            __syncthreads();
        }
    }
    grid_barrier();

    // ================= PHASE 5: layernorm(batch-dim) + relu =================
    {
        const float inv = 1.0f / (float)Bb;
        for (int idx = blockIdx.x * NTHR + tid; idx < Bb * Aa / 4; idx += NBLK * NTHR) {
            int a = (idx * 4) & (Aa - 1);
            float4 v  = reinterpret_cast<const float4*>(g_y)[idx];
            float4 s4 = *reinterpret_cast<const float4*>(&g_sum[a]);
            float4 q4 = *reinterpret_cast<const float4*>(&g_sumsq[a]);
            float4 gm = *reinterpret_cast<const float4*>(&gamma[a]);
            float4 bt = *reinterpret_cast<const float4*>(&beta[a]);
            float4 o;
            {
                float mu = s4.x * inv, var = q4.x * inv - mu * mu;
                float sc = gm.x * rsqrtf(var + 1e-5f);
                o.x = fmaxf(fmaf(v.x, sc, bt.x - mu * sc), 0.f);
            }
            {
                float mu = s4.y * inv, var = q4.y * inv - mu * mu;
                float sc = gm.y * rsqrtf(var + 1e-5f);
                o.y = fmaxf(fmaf(v.y, sc, bt.y - mu * sc), 0.f);
            }
            {
                float mu = s4.z * inv, var = q4.z * inv - mu * mu;
                float sc = gm.z * rsqrtf(var + 1e-5f);
                o.z = fmaxf(fmaf(v.z, sc, bt.z - mu * sc), 0.f);
            }
            {
                float mu = s4.w * inv, var = q4.w * inv - mu * mu;
                float sc = gm.w * rsqrtf(var + 1e-5f);
                o.w = fmaxf(fmaf(v.w, sc, bt.w - mu * sc), 0.f);
            }
            reinterpret_cast<float4*>(out)[idx] = o;
        }
    }
}

// ---------------------------------------------------------------------------
extern "C" void kernel_launch(void* const* d_in, const int* in_sizes, int n_in,
                              void* d_out, int out_size) {
    const float* h_states = (const float*)d_in[0];   // (1,B,H)
    const float* end_pos  = (const float*)d_in[1];   // (B,2)
    const float* rel_pos  = (const float*)d_in[2];   // (B,2)
    const float* scene    = (const float*)d_in[3];   // (S,P,2)
    const float* W_enc    = (const float*)d_in[4];   // (1,A)
    const float* b_enc    = (const float*)d_in[5];   // (A)
    const float* W_dec    = (const float*)d_in[6];   // (H,A)
    const float* b_dec    = (const float*)d_in[7];   // (A)
    const float* w_full   = (const float*)d_in[8];   // (A,1)
    // d_in[9]  = b_full (softmax-shift invariant -> unused)
    const float* W_out    = (const float*)d_in[10];  // (69,A)
    const float* b_out    = (const float*)d_in[11];  // (A)
    const float* W_mlp    = (const float*)d_in[12];  // (A,A)
    const float* b_mlp    = (const float*)d_in[13];  // (A)
    const float* gamma    = (const float*)d_in[14];  // (A)
    const float* beta     = (const float*)d_in[15];  // (A)
    float* out = (float*)d_out;

    // Single persistent kernel: one graph node, grid barriers between phases.
    fused_kernel<<<NBLK, NTHR>>>(h_states, end_pos, rel_pos, scene,
                                 W_enc, b_enc, W_dec, b_dec, w_full,
                                 W_out, b_out, W_mlp, b_mlp, gamma, beta, out);
}

// round 12
// speedup vs baseline: 1.3262x; 1.3262x over previous
#include <cuda_runtime.h>
#include <math.h>

// Problem constants
#define G2   64
#define Hh   64
#define Aa   1024
#define Ss   32
#define Pp   4096
#define Bb   2048
#define KS   32

typedef unsigned long long ull;

// -------- packed f32x2 helpers --------
__device__ __forceinline__ ull pk2(float lo, float hi) {
    ull r; asm("mov.b64 %0, {%1,%2};" : "=l"(r) : "f"(lo), "f"(hi)); return r;
}
__device__ __forceinline__ void upk2(ull v, float& lo, float& hi) {
    asm("mov.b64 {%0,%1}, %2;" : "=f"(lo), "=f"(hi) : "l"(v));
}
__device__ __forceinline__ ull ffma2(ull a, ull b, ull c) {
    ull d; asm("fma.rn.f32x2 %0, %1, %2, %3;" : "=l"(d) : "l"(a), "l"(b), "l"(c));
    return d;
}

// -------- device scratch (no allocations allowed) --------
__device__ float g_occ[Bb * G2];
__device__ float g_c[Bb * Aa];
__device__ float g_ctx[Bb];
__device__ float g_wc[70 * Aa];
__device__ float g_y[Bb * Aa];
__device__ float g_sum[Aa];
__device__ float g_sumsq[Aa];

// ---------------------------------------------------------------------------
// NODE 1: c = h@W_dec + b_dec + b_enc, PLUS zero g_occ/g_wc/g_sum/g_sumsq.
__global__ __launch_bounds__(256) void prep_kernel(const float* __restrict__ h,
                                                   const float* __restrict__ Wd,
                                                   const float* __restrict__ bd,
                                                   const float* __restrict__ be) {
    {
        int gidx = (blockIdx.y * 4 + blockIdx.x) * 256 + threadIdx.x;
        const float4 z = make_float4(0.f, 0.f, 0.f, 0.f);
        if (gidx < 32768) {
            reinterpret_cast<float4*>(g_occ)[gidx] = z;
        } else if (gidx < 32768 + 17920) {
            reinterpret_cast<float4*>(g_wc)[gidx - 32768] = z;
        } else if (gidx < 32768 + 17920 + 256) {
            reinterpret_cast<float4*>(g_sum)[gidx - 32768 - 17920] = z;
        } else if (gidx < 32768 + 17920 + 512) {
            reinterpret_cast<float4*>(g_sumsq)[gidx - 32768 - 17920 - 256] = z;
        }
    }

    int a  = blockIdx.x * 256 + threadIdx.x;
    int b0 = blockIdx.y * 16;
    __shared__ __align__(16) float hp[Hh * 16];
    for (int idx = threadIdx.x; idx < 16 * Hh; idx += 256) {
        int bl = idx >> 6, k = idx & 63;
        hp[k * 16 + bl] = h[(b0 + bl) * Hh + k];
    }
    __syncthreads();

    ull acc[8] = {0, 0, 0, 0, 0, 0, 0, 0};
    const ulonglong2* hpu = reinterpret_cast<const ulonglong2*>(hp);
#pragma unroll 8
    for (int k = 0; k < Hh; k++) {
        float w = Wd[k * Aa + a];
        ull ww = pk2(w, w);
#pragma unroll
        for (int jj = 0; jj < 4; jj++) {
            ulonglong2 v = hpu[k * 4 + jj];
            acc[2 * jj]     = ffma2(v.x, ww, acc[2 * jj]);
            acc[2 * jj + 1] = ffma2(v.y, ww, acc[2 * jj + 1]);
        }
    }
    float bias = bd[a] + be[a];
#pragma unroll
    for (int j = 0; j < 8; j++) {
        float lo, hi; upk2(acc[j], lo, hi);
        g_c[(size_t)(b0 + 2 * j) * Aa + a]     = lo + bias;
        g_c[(size_t)(b0 + 2 * j + 1) * Aa + a] = hi + bias;
    }
}

// ---------------------------------------------------------------------------
// NODE 2: fat kernel — blocks [0,256): occupancy; [256,768): Wc atomics.
__global__ __launch_bounds__(256) void occwc_kernel(const float* __restrict__ end_pos,
                                                    const float* __restrict__ scene,
                                                    const float* __restrict__ Wo,
                                                    const float* __restrict__ bo,
                                                    const float* __restrict__ Wm) {
    if (blockIdx.x < 256) {
        int grp = blockIdx.x & 7;
        int s   = blockIdx.x >> 3;
        int pedbase = s * 64 + grp * 8;

        __shared__ int bins[8][G2];
        __shared__ float4 boxsh[8];
        for (int i = threadIdx.x; i < 8 * G2; i += 256) ((int*)bins)[i] = 0;
        if (threadIdx.x < 8) {
            float ex = end_pos[(pedbase + threadIdx.x) * 2 + 0];
            float ey = end_pos[(pedbase + threadIdx.x) * 2 + 1];
            boxsh[threadIdx.x] = make_float4(ex - 1.0f, ey + 1.0f, ex + 1.0f, ey - 1.0f);
        }
        __syncthreads();

        float4 bx[8];
#pragma unroll
        for (int j = 0; j < 8; j++) bx[j] = boxsh[j];

        const float2* sc = reinterpret_cast<const float2*>(scene) + (size_t)s * Pp;
        for (int p = threadIdx.x; p < Pp; p += 256) {
            float2 q = sc[p];
#pragma unroll
            for (int j = 0; j < 8; j++) {
                bool in = (q.x < bx[j].z) && (q.x > bx[j].x) &&
                          (q.y < bx[j].y) && (q.y > bx[j].w);
                if (in) {
                    float cx = floorf(((q.x - bx[j].x) / 2.0f) * 8.0f);
                    float cy = floorf(((bx[j].y - q.y) / 2.0f) * 8.0f);
                    int cell = (int)(cx + cy * 8.0f);
                    if (cell >= 0 && cell < G2) {
                        atomicAdd(&bins[j][cell], 1);
                    } else {
                        long flat = (long)(pedbase + j) * G2 + cell;
                        if (flat >= 0 && flat < (long)Bb * G2)
                            atomicAdd(&g_occ[flat], 1.0f);   // rare bleed, exact int adds
                    }
                }
            }
        }
        __syncthreads();
        for (int i = threadIdx.x; i < 8 * G2; i += 256) {
            int v = ((int*)bins)[i];
            if (v) atomicAdd(&g_occ[pedbase * G2 + i], (float)v);
        }
    } else {
        int wcb = blockIdx.x - 256;          // 0..511
        int a   = (wcb & 3) * 256 + threadIdx.x;
        int r0  = ((wcb >> 2) & 3) * 18;
        int k0  = (wcb >> 4) * 32;
        __shared__ __align__(16) float ws[9 * 32 * 2];

        for (int idx = threadIdx.x; idx < 9 * 32; idx += 256) {
            int p = idx >> 5, k = idx & 31;
            int r = r0 + 2 * p;
            float v0 = 0.f, v1 = 0.f;
            if (r < 69)       v0 = Wo[r * Aa + k0 + k];
            else if (r == 69) v0 = bo[k0 + k];
            if (r + 1 < 69)       v1 = Wo[(r + 1) * Aa + k0 + k];
            else if (r + 1 == 69) v1 = bo[k0 + k];
            ws[idx * 2]     = v0;
            ws[idx * 2 + 1] = v1;
        }
        __syncthreads();

        ull acc[9];
#pragma unroll
        for (int p = 0; p < 9; p++) acc[p] = 0ull;

        const ulonglong2* wsu = reinterpret_cast<const ulonglong2*>(ws);
#pragma unroll 2
        for (int k = 0; k < 32; k += 2) {
            float w0 = Wm[(size_t)(k0 + k) * Aa + a];
            float w1 = Wm[(size_t)(k0 + k + 1) * Aa + a];
            ull ww0 = pk2(w0, w0), ww1 = pk2(w1, w1);
#pragma unroll
            for (int p = 0; p < 9; p++) {
                ulonglong2 v = wsu[p * 16 + (k >> 1)];
                acc[p] = ffma2(v.x, ww0, acc[p]);
                acc[p] = ffma2(v.y, ww1, acc[p]);
            }
        }
#pragma unroll
        for (int p = 0; p < 9; p++) {
            int r = r0 + 2 * p;
            float lo, hi; upk2(acc[p], lo, hi);
            if (r < 70)     atomicAdd(&g_wc[r * Aa + a], lo);
            if (r + 1 < 70) atomicAdd(&g_wc[(r + 1) * Aa + a], hi);
        }
    }
}

// ---------------------------------------------------------------------------
// NODE 3: fused e / softmax / ctx.
//   4 b-rows x 64 g-lanes per block, 256 threads, grid B/4 = 512.
//   (4x the parallelism of the old 8x16 layout -> ~43% occ.)
__global__ __launch_bounds__(256) void ectx_kernel(const float* __restrict__ We,
                                                   const float* __restrict__ wf) {
    int b0  = blockIdx.x * 4;
    int tid = threadIdx.x;
    int bl  = tid >> 6;   // 0..3 local row
    int gq  = tid & 63;   // grid cell
    int b   = b0 + bl;

    __shared__ __align__(16) float we_s[128], wf_s[128];
    __shared__ __align__(16) float c_s[4][132];
    __shared__ float redm[8], reds[8], redc[8];

    float og = g_occ[b * G2 + gq];
    ull ogw = pk2(og, og);
    ull e2  = 0ull;

    for (int a0 = 0; a0 < Aa; a0 += 128) {
        __syncthreads();
        if (tid < 128) { we_s[tid] = We[a0 + tid]; wf_s[tid] = wf[a0 + tid]; }
        for (int i = tid; i < 4 * 128; i += 256) {
            int bi = i >> 7, j = i & 127;
            c_s[bi][j] = g_c[(size_t)(b0 + bi) * Aa + a0 + j];
        }
        __syncthreads();
        const ull* weu = reinterpret_cast<const ull*>(we_s);
        const ull* wfu = reinterpret_cast<const ull*>(wf_s);
        const ull* cu  = reinterpret_cast<const ull*>(&c_s[bl][0]);
#pragma unroll 8
        for (int jj = 0; jj < 64; jj++) {
            ull x2 = ffma2(ogw, weu[jj], cu[jj]);
            float lo, hi; upk2(x2, lo, hi);
            lo = fmaxf(lo, 0.0f);
            hi = fmaxf(hi, 0.0f);
            e2 = ffma2(pk2(lo, hi), wfu[jj], e2);
        }
    }
    float elo, ehi; upk2(e2, elo, ehi);
    float e = elo + ehi;

    int warp = tid >> 5;
    // softmax over 64 lanes = 2 warps: warp shuffle + smem combine
    float m = e;
#pragma unroll
    for (int off = 16; off >= 1; off >>= 1)
        m = fmaxf(m, __shfl_xor_sync(0xffffffffu, m, off));
    if ((tid & 31) == 0) redm[warp] = m;
    __syncthreads();
    m = fmaxf(redm[2 * bl], redm[2 * bl + 1]);

    float ex = __expf(e - m);
    float s = ex, cx = ex * og;
#pragma unroll
    for (int off = 16; off >= 1; off >>= 1) {
        s  += __shfl_xor_sync(0xffffffffu, s, off);
        cx += __shfl_xor_sync(0xffffffffu, cx, off);
    }
    if ((tid & 31) == 0) { reds[warp] = s; redc[warp] = cx; }
    __syncthreads();
    if (gq == 0)
        g_ctx[b] = (redc[2 * bl] + redc[2 * bl + 1]) /
                   (reds[2 * bl] + reds[2 * bl + 1]);
}

// ---------------------------------------------------------------------------
// NODE 4: y = u@Wc + bias, stats atomics. 4-deep weight prefetch (MLP=4).
__global__ __launch_bounds__(128) void y_kernel(const float* __restrict__ h,
                                                const float* __restrict__ ep,
                                                const float* __restrict__ rp,
                                                const float* __restrict__ bm) {
    int a  = blockIdx.x * 128 + threadIdx.x;
    int b0 = blockIdx.y * 16;
    __shared__ __align__(16) float us[69 * 16];
    for (int idx = threadIdx.x; idx < 69 * 16; idx += 128) {
        int r = idx >> 4, bl = idx & 15;
        int b = b0 + bl;
        float v;
        if (r == 0)      v = g_ctx[b];
        else if (r < 65) v = h[b * Hh + (r - 1)];
        else if (r < 67) v = ep[b * 2 + (r - 65)];
        else             v = rp[b * 2 + (r - 67)];
        us[idx] = v;
    }
    __syncthreads();

    ull acc[8] = {0, 0, 0, 0, 0, 0, 0, 0};
    const ulonglong2* usu = reinterpret_cast<const ulonglong2*>(us);
    const float* wcol = g_wc + a;
    for (int r = 0; r < 68; r += 4) {
        float w0 = wcol[(r + 0) * Aa];
        float w1 = wcol[(r + 1) * Aa];
        float w2 = wcol[(r + 2) * Aa];
        float w3 = wcol[(r + 3) * Aa];
        ull wwv[4] = { pk2(w0, w0), pk2(w1, w1), pk2(w2, w2), pk2(w3, w3) };
#pragma unroll
        for (int rr = 0; rr < 4; rr++) {
#pragma unroll
            for (int jj = 0; jj < 4; jj++) {
                ulonglong2 v = usu[(r + rr) * 4 + jj];
                acc[2 * jj]     = ffma2(v.x, wwv[rr], acc[2 * jj]);
                acc[2 * jj + 1] = ffma2(v.y, wwv[rr], acc[2 * jj + 1]);
            }
        }
    }
    {
        float w = wcol[68 * Aa];
        ull ww = pk2(w, w);
#pragma unroll
        for (int jj = 0; jj < 4; jj++) {
            ulonglong2 v = usu[68 * 4 + jj];
            acc[2 * jj]     = ffma2(v.x, ww, acc[2 * jj]);
            acc[2 * jj + 1] = ffma2(v.y, ww, acc[2 * jj + 1]);
        }
    }
    float bias = wcol[69 * Aa] + bm[a];
    float s = 0.f, s2 = 0.f;
#pragma unroll
    for (int j = 0; j < 8; j++) {
        float lo, hi; upk2(acc[j], lo, hi);
        float v0 = lo + bias, v1 = hi + bias;
        g_y[(size_t)(b0 + 2 * j) * Aa + a]     = v0;
        g_y[(size_t)(b0 + 2 * j + 1) * Aa + a] = v1;
        s += v0 + v1;
        s2 = fmaf(v0, v0, s2);
        s2 = fmaf(v1, v1, s2);
    }
    atomicAdd(&g_sum[a], s);
    atomicAdd(&g_sumsq[a], s2);
}

// ---------------------------------------------------------------------------
// NODE 5: out = relu(layernorm_batchdim(y)), stats recomputed inline.
__global__ __launch_bounds__(256) void finalize_kernel(const float* __restrict__ gamma,
                                                       const float* __restrict__ beta,
                                                       float* __restrict__ out) {
    int idx = blockIdx.x * blockDim.x + threadIdx.x;
    const int n = Bb * Aa / 4;
    if (idx >= n) return;
    int a = (idx * 4) & (Aa - 1);
    float4 v  = reinterpret_cast<const float4*>(g_y)[idx];
    float4 s4 = *reinterpret_cast<const float4*>(&g_sum[a]);
    float4 q4 = *reinterpret_cast<const float4*>(&g_sumsq[a]);
    float4 gm = *reinterpret_cast<const float4*>(&gamma[a]);
    float4 bt = *reinterpret_cast<const float4*>(&beta[a]);
    const float inv = 1.0f / (float)Bb;
    float4 o;
    {
        float mu = s4.x * inv, var = q4.x * inv - mu * mu;
        float sc = gm.x * rsqrtf(var + 1e-5f);
        o.x = fmaxf(fmaf(v.x, sc, bt.x - mu * sc), 0.f);
    }
    {
        float mu = s4.y * inv, var = q4.y * inv - mu * mu;
        float sc = gm.y * rsqrtf(var + 1e-5f);
        o.y = fmaxf(fmaf(v.y, sc, bt.y - mu * sc), 0.f);
    }
    {
        float mu = s4.z * inv, var = q4.z * inv - mu * mu;
        float sc = gm.z * rsqrtf(var + 1e-5f);
        o.z = fmaxf(fmaf(v.z, sc, bt.z - mu * sc), 0.f);
    }
    {
        float mu = s4.w * inv, var = q4.w * inv - mu * mu;
        float sc = gm.w * rsqrtf(var + 1e-5f);
        o.w = fmaxf(fmaf(v.w, sc, bt.w - mu * sc), 0.f);
    }
    reinterpret_cast<float4*>(out)[idx] = o;
}

// ---------------------------------------------------------------------------
extern "C" void kernel_launch(void* const* d_in, const int* in_sizes, int n_in,
                              void* d_out, int out_size) {
    const float* h_states = (const float*)d_in[0];   // (1,B,H)
    const float* end_pos  = (const float*)d_in[1];   // (B,2)
    const float* rel_pos  = (const float*)d_in[2];   // (B,2)
    const float* scene    = (const float*)d_in[3];   // (S,P,2)
    const float* W_enc    = (const float*)d_in[4];   // (1,A)
    const float* b_enc    = (const float*)d_in[5];   // (A)
    const float* W_dec    = (const float*)d_in[6];   // (H,A)
    const float* b_dec    = (const float*)d_in[7];   // (A)
    const float* w_full   = (const float*)d_in[8];   // (A,1)
    // d_in[9]  = b_full (softmax-shift invariant -> unused)
    const float* W_out    = (const float*)d_in[10];  // (69,A)
    const float* b_out    = (const float*)d_in[11];  // (A)
    const float* W_mlp    = (const float*)d_in[12];  // (A,A)
    const float* b_mlp    = (const float*)d_in[13];  // (A)
    const float* gamma    = (const float*)d_in[14];  // (A)
    const float* beta     = (const float*)d_in[15];  // (A)
    float* out = (float*)d_out;

    prep_kernel<<<dim3(4, 128), 256>>>(h_states, W_dec, b_dec, b_enc);
    occwc_kernel<<<256 + 512, 256>>>(end_pos, scene, W_out, b_out, W_mlp);
    ectx_kernel<<<Bb / 4, 256>>>(W_enc, w_full);
    y_kernel<<<dim3(Aa / 128, Bb / 16), 128>>>(h_states, end_pos, rel_pos, b_mlp);
    finalize_kernel<<<(Bb * Aa / 4 + 255) / 256, 256>>>(gamma, beta, out);
}

// round 14
// speedup vs baseline: 1.5137x; 1.1414x over previous
#include <cuda_runtime.h>
#include <math.h>

// Problem constants
#define G2   64
#define Hh   64
#define Aa   1024
#define Ss   32
#define Pp   4096
#define Bb   2048
#define BMAX 512   // occupancy-count bucket range for ectx

typedef unsigned long long ull;

// -------- packed f32x2 helpers --------
__device__ __forceinline__ ull pk2(float lo, float hi) {
    ull r; asm("mov.b64 %0, {%1,%2};" : "=l"(r) : "f"(lo), "f"(hi)); return r;
}
__device__ __forceinline__ void upk2(ull v, float& lo, float& hi) {
    asm("mov.b64 {%0,%1}, %2;" : "=f"(lo), "=f"(hi) : "l"(v));
}
__device__ __forceinline__ ull ffma2(ull a, ull b, ull c) {
    ull d; asm("fma.rn.f32x2 %0, %1, %2, %3;" : "=l"(d) : "l"(a), "l"(b), "l"(c));
    return d;
}

// -------- device scratch (no allocations allowed) --------
__device__ float g_occ[Bb * G2];
__device__ float g_c[Bb * Aa];
__device__ float g_ctx[Bb];
__device__ float g_wc[70 * Aa];
__device__ float g_y[Bb * Aa];
__device__ float g_sum[Aa];
__device__ float g_sumsq[Aa];

// ---------------------------------------------------------------------------
// NODE 1: c = h@W_dec + b_dec + b_enc, PLUS zero g_occ/g_wc/g_sum/g_sumsq.
__global__ __launch_bounds__(256) void prep_kernel(const float* __restrict__ h,
                                                   const float* __restrict__ Wd,
                                                   const float* __restrict__ bd,
                                                   const float* __restrict__ be) {
    {
        int gidx = (blockIdx.y * 4 + blockIdx.x) * 256 + threadIdx.x;
        const float4 z = make_float4(0.f, 0.f, 0.f, 0.f);
        if (gidx < 32768) {
            reinterpret_cast<float4*>(g_occ)[gidx] = z;
        } else if (gidx < 32768 + 17920) {
            reinterpret_cast<float4*>(g_wc)[gidx - 32768] = z;
        } else if (gidx < 32768 + 17920 + 256) {
            reinterpret_cast<float4*>(g_sum)[gidx - 32768 - 17920] = z;
        } else if (gidx < 32768 + 17920 + 512) {
            reinterpret_cast<float4*>(g_sumsq)[gidx - 32768 - 17920 - 256] = z;
        }
    }

    int a  = blockIdx.x * 256 + threadIdx.x;
    int b0 = blockIdx.y * 16;
    __shared__ __align__(16) float hp[Hh * 16];
    for (int idx = threadIdx.x; idx < 16 * Hh; idx += 256) {
        int bl = idx >> 6, k = idx & 63;
        hp[k * 16 + bl] = h[(b0 + bl) * Hh + k];
    }
    __syncthreads();

    ull acc[8] = {0, 0, 0, 0, 0, 0, 0, 0};
    const ulonglong2* hpu = reinterpret_cast<const ulonglong2*>(hp);
#pragma unroll 8
    for (int k = 0; k < Hh; k++) {
        float w = Wd[k * Aa + a];
        ull ww = pk2(w, w);
#pragma unroll
        for (int jj = 0; jj < 4; jj++) {
            ulonglong2 v = hpu[k * 4 + jj];
            acc[2 * jj]     = ffma2(v.x, ww, acc[2 * jj]);
            acc[2 * jj + 1] = ffma2(v.y, ww, acc[2 * jj + 1]);
        }
    }
    float bias = bd[a] + be[a];
#pragma unroll
    for (int j = 0; j < 8; j++) {
        float lo, hi; upk2(acc[j], lo, hi);
        g_c[(size_t)(b0 + 2 * j) * Aa + a]     = lo + bias;
        g_c[(size_t)(b0 + 2 * j + 1) * Aa + a] = hi + bias;
    }
}

// ---------------------------------------------------------------------------
// NODE 2: fat kernel — blocks [0,256): occupancy; [256,768): Wc atomics.
__global__ __launch_bounds__(256) void occwc_kernel(const float* __restrict__ end_pos,
                                                    const float* __restrict__ scene,
                                                    const float* __restrict__ Wo,
                                                    const float* __restrict__ bo,
                                                    const float* __restrict__ Wm) {
    if (blockIdx.x < 256) {
        int grp = blockIdx.x & 7;
        int s   = blockIdx.x >> 3;
        int pedbase = s * 64 + grp * 8;

        __shared__ int bins[8][G2];
        __shared__ float4 boxsh[8];
        for (int i = threadIdx.x; i < 8 * G2; i += 256) ((int*)bins)[i] = 0;
        if (threadIdx.x < 8) {
            float ex = end_pos[(pedbase + threadIdx.x) * 2 + 0];
            float ey = end_pos[(pedbase + threadIdx.x) * 2 + 1];
            boxsh[threadIdx.x] = make_float4(ex - 1.0f, ey + 1.0f, ex + 1.0f, ey - 1.0f);
        }
        __syncthreads();

        float4 bx[8];
#pragma unroll
        for (int j = 0; j < 8; j++) bx[j] = boxsh[j];

        const float2* sc = reinterpret_cast<const float2*>(scene) + (size_t)s * Pp;
        for (int p = threadIdx.x; p < Pp; p += 256) {
            float2 q = sc[p];
#pragma unroll
            for (int j = 0; j < 8; j++) {
                bool in = (q.x < bx[j].z) && (q.x > bx[j].x) &&
                          (q.y < bx[j].y) && (q.y > bx[j].w);
                if (in) {
                    float cx = floorf(((q.x - bx[j].x) / 2.0f) * 8.0f);
                    float cy = floorf(((bx[j].y - q.y) / 2.0f) * 8.0f);
                    int cell = (int)(cx + cy * 8.0f);
                    if (cell >= 0 && cell < G2) {
                        atomicAdd(&bins[j][cell], 1);
                    } else {
                        long flat = (long)(pedbase + j) * G2 + cell;
                        if (flat >= 0 && flat < (long)Bb * G2)
                            atomicAdd(&g_occ[flat], 1.0f);   // rare bleed, exact int adds
                    }
                }
            }
        }
        __syncthreads();
        for (int i = threadIdx.x; i < 8 * G2; i += 256) {
            int v = ((int*)bins)[i];
            if (v) atomicAdd(&g_occ[pedbase * G2 + i], (float)v);
        }
    } else {
        int wcb = blockIdx.x - 256;          // 0..511
        int a   = (wcb & 3) * 256 + threadIdx.x;
        int r0  = ((wcb >> 2) & 3) * 18;
        int k0  = (wcb >> 4) * 32;
        __shared__ __align__(16) float ws[9 * 32 * 2];

        for (int idx = threadIdx.x; idx < 9 * 32; idx += 256) {
            int p = idx >> 5, k = idx & 31;
            int r = r0 + 2 * p;
            float v0 = 0.f, v1 = 0.f;
            if (r < 69)       v0 = Wo[r * Aa + k0 + k];
            else if (r == 69) v0 = bo[k0 + k];
            if (r + 1 < 69)       v1 = Wo[(r + 1) * Aa + k0 + k];
            else if (r + 1 == 69) v1 = bo[k0 + k];
            ws[idx * 2]     = v0;
            ws[idx * 2 + 1] = v1;
        }
        __syncthreads();

        ull acc[9];
#pragma unroll
        for (int p = 0; p < 9; p++) acc[p] = 0ull;

        const ulonglong2* wsu = reinterpret_cast<const ulonglong2*>(ws);
#pragma unroll 2
        for (int k = 0; k < 32; k += 2) {
            float w0 = Wm[(size_t)(k0 + k) * Aa + a];
            float w1 = Wm[(size_t)(k0 + k + 1) * Aa + a];
            ull ww0 = pk2(w0, w0), ww1 = pk2(w1, w1);
#pragma unroll
            for (int p = 0; p < 9; p++) {
                ulonglong2 v = wsu[p * 16 + (k >> 1)];
                acc[p] = ffma2(v.x, ww0, acc[p]);
                acc[p] = ffma2(v.y, ww1, acc[p]);
            }
        }
#pragma unroll
        for (int p = 0; p < 9; p++) {
            int r = r0 + 2 * p;
            float lo, hi; upk2(acc[p], lo, hi);
            if (r < 70)     atomicAdd(&g_wc[r * Aa + a], lo);
            if (r + 1 < 70) atomicAdd(&g_wc[(r + 1) * Aa + a], hi);
        }
    }
}

// ---------------------------------------------------------------------------
// NODE 3: ectx via activation-threshold bucketing.
//   e[b,g] = sum_a relu(og*We_a + c_a)*wf_a depends on the cell only through
//   the integer count t = og. Each a-term is linear in t with one activation
//   threshold tau = -c/We. Bucket activation deltas over t in [0,BMAX), prefix
//   sum, then e(t) = A(t)*t + C(t). One block (128 thr) per row, grid = B.
__global__ __launch_bounds__(128) void ectx_kernel(const float* __restrict__ We,
                                                   const float* __restrict__ wf) {
    __shared__ float Ad[BMAX], Cd[BMAX];
    __shared__ float sA[128], sC[128];
    __shared__ float redm[4], reds[4], redc[4];

    const int b   = blockIdx.x;
    const int tid = threadIdx.x;
    const float* crow = g_c + (size_t)b * Aa;

    for (int i = tid; i < BMAX; i += 128) { Ad[i] = 0.f; Cd[i] = 0.f; }
    __syncthreads();

    // ---- scatter activation deltas; always-active terms stay in registers ----
    float A0 = 0.f, C0 = 0.f;
    for (int a = tid; a < Aa; a += 128) {
        float we = We[a], w = wf[a], c = crow[a];
        float wewf = we * w, cwf = c * w;
        if (we > 0.f) {
            float tau = __fdividef(-c, we);          // active for t > tau
            if (tau < 0.f) { A0 += wewf; C0 += cwf; }
            else if (tau < (float)(BMAX - 1)) {
                int t0 = (int)tau + 1;               // first active integer
                atomicAdd(&Ad[t0], wewf);
                atomicAdd(&Cd[t0], cwf);
            }
            // tau >= BMAX-1: no bucketed cell active (fallback handles t>=BMAX)
        } else if (we < 0.f) {
            float tau = __fdividef(-c, we);          // active for t < tau
            if (tau >= (float)(BMAX - 1)) { A0 += wewf; C0 += cwf; }
            else if (tau > 0.f) {
                A0 += wewf; C0 += cwf;
                int t1 = (int)ceilf(tau);            // deactivate from t1 on
                atomicAdd(&Ad[t1], -wewf);
                atomicAdd(&Cd[t1], -cwf);
            }
            // tau <= 0: never active
        } else if (c > 0.f) {
            C0 += cwf;                               // We == 0, constant term
        }
    }
    // warp-reduce A0/C0, deposit into bucket 0
#pragma unroll
    for (int off = 16; off >= 1; off >>= 1) {
        A0 += __shfl_xor_sync(0xffffffffu, A0, off);
        C0 += __shfl_xor_sync(0xffffffffu, C0, off);
    }
    if ((tid & 31) == 0) { atomicAdd(&Ad[0], A0); atomicAdd(&Cd[0], C0); }
    __syncthreads();

    // ---- inclusive prefix sum over BMAX buckets (4 per thread + block scan) ----
    int base = tid * 4;
    float pa0 = Ad[base], pa1 = Ad[base + 1], pa2 = Ad[base + 2], pa3 = Ad[base + 3];
    float pc0 = Cd[base], pc1 = Cd[base + 1], pc2 = Cd[base + 2], pc3 = Cd[base + 3];
    pa1 += pa0; pa2 += pa1; pa3 += pa2;
    pc1 += pc0; pc2 += pc1; pc3 += pc2;
    sA[tid] = pa3; sC[tid] = pc3;
    __syncthreads();
    for (int off = 1; off < 128; off <<= 1) {
        float va = (tid >= off) ? sA[tid - off] : 0.f;
        float vc = (tid >= off) ? sC[tid - off] : 0.f;
        __syncthreads();
        sA[tid] += va; sC[tid] += vc;
        __syncthreads();
    }
    float offA = sA[tid] - pa3, offC = sC[tid] - pc3;
    Ad[base] = pa0 + offA; Ad[base + 1] = pa1 + offA;
    Ad[base + 2] = pa2 + offA; Ad[base + 3] = pa3 + offA;
    Cd[base] = pc0 + offC; Cd[base + 1] = pc1 + offC;
    Cd[base + 2] = pc2 + offC; Cd[base + 3] = pc3 + offC;
    __syncthreads();

    // ---- evaluate e per cell, then softmax + ctx ----
    float e = -1e30f, ogv = 0.f;
    if (tid < G2) {
        ogv = g_occ[b * G2 + tid];
        int t = (int)ogv;
        if (t < BMAX) {
            e = Ad[t] * ogv + Cd[t];
        } else {            // exact fallback (unreachable with this data)
            e = 0.f;
            for (int a = 0; a < Aa; a++)
                e = fmaf(fmaxf(fmaf(ogv, We[a], crow[a]), 0.f), wf[a], e);
        }
    }
    int warp = tid >> 5;
    float m = e;
#pragma unroll
    for (int off = 16; off >= 1; off >>= 1)
        m = fmaxf(m, __shfl_xor_sync(0xffffffffu, m, off));
    if ((tid & 31) == 0) redm[warp] = m;
    __syncthreads();
    m = fmaxf(fmaxf(redm[0], redm[1]), fmaxf(redm[2], redm[3]));

    float ex = __expf(e - m);        // lanes >= 64: exp(-huge) = 0
    float s = ex, cx = ex * ogv;
#pragma unroll
    for (int off = 16; off >= 1; off >>= 1) {
        s  += __shfl_xor_sync(0xffffffffu, s, off);
        cx += __shfl_xor_sync(0xffffffffu, cx, off);
    }
    if ((tid & 31) == 0) { reds[warp] = s; redc[warp] = cx; }
    __syncthreads();
    if (tid == 0)
        g_ctx[b] = (redc[0] + redc[1] + redc[2] + redc[3]) /
                   (reds[0] + reds[1] + reds[2] + reds[3]);
}

// ---------------------------------------------------------------------------
// NODE 4: y = u@Wc + bias, stats atomics. 8-row tiles for ~86% occupancy.
__global__ __launch_bounds__(128) void y_kernel(const float* __restrict__ h,
                                                const float* __restrict__ ep,
                                                const float* __restrict__ rp,
                                                const float* __restrict__ bm) {
    int a  = blockIdx.x * 128 + threadIdx.x;
    int b0 = blockIdx.y * 8;
    __shared__ __align__(16) float us[69 * 8];
    for (int idx = threadIdx.x; idx < 69 * 8; idx += 128) {
        int r = idx >> 3, bl = idx & 7;
        int b = b0 + bl;
        float v;
        if (r == 0)      v = g_ctx[b];
        else if (r < 65) v = h[b * Hh + (r - 1)];
        else if (r < 67) v = ep[b * 2 + (r - 65)];
        else             v = rp[b * 2 + (r - 67)];
        us[idx] = v;
    }
    __syncthreads();

    ull acc[4] = {0, 0, 0, 0};
    const ulonglong2* usu = reinterpret_cast<const ulonglong2*>(us);
    const float* wcol = g_wc + a;
    for (int r = 0; r < 68; r += 4) {
        float w0 = wcol[(r + 0) * Aa];
        float w1 = wcol[(r + 1) * Aa];
        float w2 = wcol[(r + 2) * Aa];
        float w3 = wcol[(r + 3) * Aa];
        ull wwv[4] = { pk2(w0, w0), pk2(w1, w1), pk2(w2, w2), pk2(w3, w3) };
#pragma unroll
        for (int rr = 0; rr < 4; rr++) {
            ulonglong2 v = usu[(r + rr) * 2];
            ulonglong2 v2 = usu[(r + rr) * 2 + 1];
            acc[0] = ffma2(v.x,  wwv[rr], acc[0]);
            acc[1] = ffma2(v.y,  wwv[rr], acc[1]);
            acc[2] = ffma2(v2.x, wwv[rr], acc[2]);
            acc[3] = ffma2(v2.y, wwv[rr], acc[3]);
        }
    }
    {
        float w = wcol[68 * Aa];
        ull ww = pk2(w, w);
        ulonglong2 v = usu[68 * 2];
        ulonglong2 v2 = usu[68 * 2 + 1];
        acc[0] = ffma2(v.x,  ww, acc[0]);
        acc[1] = ffma2(v.y,  ww, acc[1]);
        acc[2] = ffma2(v2.x, ww, acc[2]);
        acc[3] = ffma2(v2.y, ww, acc[3]);
    }
    float bias = wcol[69 * Aa] + bm[a];
    float s = 0.f, s2 = 0.f;
#pragma unroll
    for (int j = 0; j < 4; j++) {
        float lo, hi; upk2(acc[j], lo, hi);
        float v0 = lo + bias, v1 = hi + bias;
        g_y[(size_t)(b0 + 2 * j) * Aa + a]     = v0;
        g_y[(size_t)(b0 + 2 * j + 1) * Aa + a] = v1;
        s += v0 + v1;
        s2 = fmaf(v0, v0, s2);
        s2 = fmaf(v1, v1, s2);
    }
    atomicAdd(&g_sum[a], s);
    atomicAdd(&g_sumsq[a], s2);
}

// ---------------------------------------------------------------------------
// NODE 5: out = relu(layernorm_batchdim(y)), stats recomputed inline.
__global__ __launch_bounds__(256) void finalize_kernel(const float* __restrict__ gamma,
                                                       const float* __restrict__ beta,
                                                       float* __restrict__ out) {
    int idx = blockIdx.x * blockDim.x + threadIdx.x;
    const int n = Bb * Aa / 4;
    if (idx >= n) return;
    int a = (idx * 4) & (Aa - 1);
    float4 v  = reinterpret_cast<const float4*>(g_y)[idx];
    float4 s4 = *reinterpret_cast<const float4*>(&g_sum[a]);
    float4 q4 = *reinterpret_cast<const float4*>(&g_sumsq[a]);
    float4 gm = *reinterpret_cast<const float4*>(&gamma[a]);
    float4 bt = *reinterpret_cast<const float4*>(&beta[a]);
    const float inv = 1.0f / (float)Bb;
    float4 o;
    {
        float mu = s4.x * inv, var = q4.x * inv - mu * mu;
        float sc = gm.x * rsqrtf(var + 1e-5f);
        o.x = fmaxf(fmaf(v.x, sc, bt.x - mu * sc), 0.f);
    }
    {
        float mu = s4.y * inv, var = q4.y * inv - mu * mu;
        float sc = gm.y * rsqrtf(var + 1e-5f);
        o.y = fmaxf(fmaf(v.y, sc, bt.y - mu * sc), 0.f);
    }
    {
        float mu = s4.z * inv, var = q4.z * inv - mu * mu;
        float sc = gm.z * rsqrtf(var + 1e-5f);
        o.z = fmaxf(fmaf(v.z, sc, bt.z - mu * sc), 0.f);
    }
    {
        float mu = s4.w * inv, var = q4.w * inv - mu * mu;
        float sc = gm.w * rsqrtf(var + 1e-5f);
        o.w = fmaxf(fmaf(v.w, sc, bt.w - mu * sc), 0.f);
    }
    reinterpret_cast<float4*>(out)[idx] = o;
}

// ---------------------------------------------------------------------------
extern "C" void kernel_launch(void* const* d_in, const int* in_sizes, int n_in,
                              void* d_out, int out_size) {
    const float* h_states = (const float*)d_in[0];   // (1,B,H)
    const float* end_pos  = (const float*)d_in[1];   // (B,2)
    const float* rel_pos  = (const float*)d_in[2];   // (B,2)
    const float* scene    = (const float*)d_in[3];   // (S,P,2)
    const float* W_enc    = (const float*)d_in[4];   // (1,A)
    const float* b_enc    = (const float*)d_in[5];   // (A)
    const float* W_dec    = (const float*)d_in[6];   // (H,A)
    const float* b_dec    = (const float*)d_in[7];   // (A)
    const float* w_full   = (const float*)d_in[8];   // (A,1)
    // d_in[9]  = b_full (softmax-shift invariant -> unused)
    const float* W_out    = (const float*)d_in[10];  // (69,A)
    const float* b_out    = (const float*)d_in[11];  // (A)
    const float* W_mlp    = (const float*)d_in[12];  // (A,A)
    const float* b_mlp    = (const float*)d_in[13];  // (A)
    const float* gamma    = (const float*)d_in[14];  // (A)
    const float* beta     = (const float*)d_in[15];  // (A)
    float* out = (float*)d_out;

    prep_kernel<<<dim3(4, 128), 256>>>(h_states, W_dec, b_dec, b_enc);
    occwc_kernel<<<256 + 512, 256>>>(end_pos, scene, W_out, b_out, W_mlp);
    ectx_kernel<<<Bb, 128>>>(W_enc, w_full);
    y_kernel<<<dim3(8, 256), 128>>>(h_states, end_pos, rel_pos, b_mlp);
    finalize_kernel<<<(Bb * Aa / 4 + 255) / 256, 256>>>(gamma, beta, out);
}